// round 14
// baseline (speedup 1.0000x reference)
#include <cuda_runtime.h>
#include <cuda_fp16.h>
#include <cstdint>

// Problem constants
constexpr int B_  = 8;
constexpr int C_  = 256;
constexpr int CI_ = 64;
constexpr int N_  = 4096;   // H*W
constexpr float LOG2E = 1.4426950408889634f;
constexpr uint32_t H2_OFF16 = 0x4C004C00u;   // f16x2 {16.0, 16.0}

// ---------------- scratch (device globals: allocation-free rule) ----------------
__device__ __half d_th[B_ * CI_ * N_];  // theta fp16 (pre-scaled by log2e) [b][ci][n]
__device__ __half d_ph[B_ * CI_ * N_];  // phi fp16 [b][ci][n]
__device__ __half d_g [B_ * CI_ * N_];  // g fp16 [b][ci][n]
__device__ __half d_y [B_ * N_ * CI_];  // attention out fp16 [b][n][ci]

// ---------------- helpers ----------------
__device__ __forceinline__ uint32_t smem_u32(const void* p) {
    uint32_t a;
    asm("{ .reg .u64 t; cvta.to.shared.u64 t, %1; cvt.u32.u64 %0, t; }" : "=r"(a) : "l"(p));
    return a;
}
__device__ __forceinline__ void mma_f16(float* c, const uint32_t* a, const uint32_t* b) {
    asm volatile(
        "mma.sync.aligned.m16n8k16.row.col.f32.f16.f16.f32 "
        "{%0,%1,%2,%3}, {%4,%5,%6,%7}, {%8,%9}, {%0,%1,%2,%3};"
        : "+f"(c[0]), "+f"(c[1]), "+f"(c[2]), "+f"(c[3])
        : "r"(a[0]), "r"(a[1]), "r"(a[2]), "r"(a[3]), "r"(b[0]), "r"(b[1]));
}
__device__ __forceinline__ void ldmx4(uint32_t* r, uint32_t addr) {
    asm volatile("ldmatrix.sync.aligned.m8n8.x4.shared.b16 {%0,%1,%2,%3}, [%4];"
                 : "=r"(r[0]), "=r"(r[1]), "=r"(r[2]), "=r"(r[3]) : "r"(addr));
}
__device__ __forceinline__ void ldmx4t(uint32_t* r, uint32_t addr) {
    asm volatile("ldmatrix.sync.aligned.m8n8.x4.trans.shared.b16 {%0,%1,%2,%3}, [%4];"
                 : "=r"(r[0]), "=r"(r[1]), "=r"(r[2]), "=r"(r[3]) : "r"(addr));
}
__device__ __forceinline__ uint32_t pack_f16x2(float lo, float hi) {
    uint32_t r;
    asm("cvt.rn.f16x2.f32 %0, %1, %2;" : "=r"(r) : "f"(hi), "f"(lo));
    return r;
}
__device__ __forceinline__ uint32_t exp2_off16(uint32_t h2) {
    asm("sub.f16x2 %0, %0, %1;" : "+r"(h2) : "r"(H2_OFF16));
    asm("ex2.approx.f16x2 %0, %0;" : "+r"(h2));
    return h2;
}
__device__ __forceinline__ uint32_t hadd2u(uint32_t a, uint32_t b) {
    uint32_t r;
    asm("add.f16x2 %0, %1, %2;" : "=r"(r) : "r"(a), "r"(b));
    return r;
}
__device__ __forceinline__ float2 h2_to_f2(uint32_t h2) {
    __half2 h = *reinterpret_cast<__half2*>(&h2);
    return __half22float2(h);
}
__device__ __forceinline__ void cp16(uint32_t s, const void* g) {
    asm volatile("cp.async.cg.shared.global [%0], [%1], 16;" :: "r"(s), "l"(g));
}
__device__ __forceinline__ void cp_commit() { asm volatile("cp.async.commit_group;"); }
template <int n> __device__ __forceinline__ void cp_wait() {
    asm volatile("cp.async.wait_group %0;" :: "n"(n));
}

// ============== Kernel 1: FUSED projections (one x pass, 3 weight sets) ==============
constexpr int PJ_WS   = 0;          // 3 * 64 * 272 = 52224
constexpr int PJ_XS   = 52224;      // 128 * 144   = 18432
constexpr int PJ_SMEM = 70656;

__global__ __launch_bounds__(384, 2) void proj_kernel(
    const float* __restrict__ x,
    const float* __restrict__ tw, const float* __restrict__ pw,
    const float* __restrict__ gw,
    const float* __restrict__ tb, const float* __restrict__ pb,
    const float* __restrict__ gb)
{
    extern __shared__ char sm[];
    const uint32_t sb = smem_u32(sm);
    const int tid = threadIdx.x;
    const int wid = tid >> 5, lane = tid & 31;
    const int nt = blockIdx.x, b = blockIdx.y;
    const int lr = lane >> 2, lc = lane & 3;

    const float* wsrc[3] = { tw, pw, gw };
    const float* xsrc = x + (size_t)b * C_ * N_ + nt * 64;

    const int pj = wid >> 2, mi = wid & 3;
    const int amr = (lane & 7) + ((lane >> 3) & 1) * 8;
    const int akc = (lane >> 4) * 8;
    const int bkr = ((lane >> 3) & 1) * 8 + (lane & 7);
    const int bnc = (lane >> 4) * 8;

    float acc[8][4];
    #pragma unroll
    for (int i = 0; i < 8; i++)
        #pragma unroll
        for (int j = 0; j < 4; j++) acc[i][j] = 0.f;

    const uint32_t ws_base = sb + PJ_WS + pj * 17408;

    for (int ch = 0; ch < 2; ch++) {
        __syncthreads();
        #pragma unroll
        for (int j = 0; j < 16; j++) {
            int idx = tid + j * 384;          // 0..6143
            int row = idx >> 5, c4 = idx & 31;
            int p = row >> 6, r = row & 63;
            float4 v = *(const float4*)(wsrc[p] + (size_t)r * C_ + ch * 128 + c4 * 4);
            uint2 o = { pack_f16x2(v.x, v.y), pack_f16x2(v.z, v.w) };
            *(uint2*)(sm + PJ_WS + p * 17408 + r * 272 + c4 * 8) = o;
        }
        #pragma unroll
        for (int j = 0; j < 6; j++) {
            int idx = tid + j * 384;          // 0..2303, guard at 2048
            if (idx < 2048) {
                int row = idx >> 4, c4 = idx & 15;
                float4 v = *(const float4*)(xsrc + (size_t)(ch * 128 + row) * N_ + c4 * 4);
                uint2 o = { pack_f16x2(v.x, v.y), pack_f16x2(v.z, v.w) };
                *(uint2*)(sm + PJ_XS + row * 144 + c4 * 8) = o;
            }
        }
        __syncthreads();

        #pragma unroll
        for (int ks = 0; ks < 8; ks++) {
            uint32_t a[4];
            ldmx4(a, ws_base + ((mi * 16 + amr) * 136 + ks * 16 + akc) * 2);
            #pragma unroll
            for (int nf4 = 0; nf4 < 4; nf4++) {
                uint32_t bb[4];
                ldmx4t(bb, sb + PJ_XS +
                           ((ks * 16 + bkr) * 72 + nf4 * 16 + bnc) * 2);
                mma_f16(acc[2 * nf4],     a, bb);
                mma_f16(acc[2 * nf4 + 1], a, bb + 2);
            }
        }
    }

    const float* bias = (pj == 0) ? tb : (pj == 1) ? pb : gb;
    const int ci0 = mi * 16 + lr;
    const float bv0 = bias[ci0], bv1 = bias[ci0 + 8];
    const float sc = (pj == 0) ? LOG2E : 1.f;

    __half* out = (pj == 0 ? d_th : (pj == 1 ? d_ph : d_g)) + (size_t)b * CI_ * N_;
    #pragma unroll
    for (int nf = 0; nf < 8; nf++) {
        size_t n = (size_t)nt * 64 + nf * 8 + lc * 2;
        *(uint32_t*)(out + (size_t)ci0 * N_ + n) =
            pack_f16x2((acc[nf][0] + bv0) * sc, (acc[nf][1] + bv0) * sc);
        *(uint32_t*)(out + (size_t)(ci0 + 8) * N_ + n) =
            pack_f16x2((acc[nf][2] + bv1) * sc, (acc[nf][3] + bv1) * sc);
    }
}

// ============== Kernel 2: flash attention, m32/warp, 3-stage, single barrier/tile ==============
constexpr int AT_TILE  = 9216;       // 64*144
constexpr int AT_STAGE = 18432;      // 2 tiles (phi + g)
constexpr int AT_SMEM  = 55296;      // 3 stages

__device__ __forceinline__ void attn_stage_issue(
    uint32_t sbase, const __half* ph, const __half* gg, int koff, int tid)
{
    #pragma unroll
    for (int j = 0; j < 8; j++) {
        int idx = tid + j * 64;              // 0..511
        int row = idx >> 3, c16 = idx & 7;
        uint32_t so = row * 144 + c16 * 16;
        cp16(sbase + so,           ph + (size_t)row * N_ + koff + c16 * 8);
        cp16(sbase + AT_TILE + so, gg + (size_t)row * N_ + koff + c16 * 8);
    }
}

__global__ __launch_bounds__(64, 4) void attn_kernel()
{
    extern __shared__ char sm[];
    const uint32_t sb = smem_u32(sm);
    const int tid = threadIdx.x;
    const int wid = tid >> 5, lane = tid & 31;
    const int nt = blockIdx.x;   // 64-query tile (0..63)
    const int b  = blockIdx.y;
    const int lr = lane >> 2, lc = lane & 3;
    const int phase = (nt & 3) << 4;   // rotated key-tile start

    const __half* ph = d_ph + (size_t)b * CI_ * N_;
    const __half* gg = d_g  + (size_t)b * CI_ * N_;
    const __half* th = d_th + (size_t)b * CI_ * N_ + nt * 64;

    // ---- theta A-frags via stage-0 region ----
    const int tkr = (lane >> 4) * 8 + (lane & 7);
    const int tmc = ((lane >> 3) & 1) * 8;
    uint32_t a[4][2][4];   // [kc][arow][frag]
    {
        #pragma unroll
        for (int j = 0; j < 8; j++) {
            int idx = tid + j * 64;
            int row = idx >> 3, c16 = idx & 7;
            *(uint4*)(sm + row * 144 + c16 * 16) =
                *(const uint4*)(th + (size_t)row * N_ + c16 * 8);
        }
        __syncthreads();
        #pragma unroll
        for (int kc = 0; kc < 4; kc++)
            #pragma unroll
            for (int ar = 0; ar < 2; ar++)
                ldmx4t(a[kc][ar],
                       sb + ((kc * 16 + tkr) * 72 + wid * 32 + ar * 16 + tmc) * 2);
        __syncthreads();
    }

    // prefetch tiles 0,1 into slots 0,1
    attn_stage_issue(sb,            ph, gg, ((0 + phase) & 63) * 64, tid); cp_commit();
    attn_stage_issue(sb + AT_STAGE, ph, gg, ((1 + phase) & 63) * 64, tid); cp_commit();

    const int bkr = ((lane >> 3) & 1) * 8 + (lane & 7);   // trans (phi)
    const int bnc = (lane >> 4) * 8;
    const int lmr = ((lane >> 4) << 3) + (lane & 7);      // non-trans (g)
    const int lmc = ((lane >> 3) & 1) * 8;

    float yacc[2][8][4];
    #pragma unroll
    for (int ar = 0; ar < 2; ar++)
        #pragma unroll
        for (int i = 0; i < 8; i++)
            #pragma unroll
            for (int j = 0; j < 4; j++) yacc[ar][i][j] = 0.f;
    float rs[2][2] = {{0.f, 0.f}, {0.f, 0.f}};

    int slot = 0;      // slot of tile kt (kt % 3)
    int slot2 = 2;     // slot of tile kt+2 ((kt+2) % 3)
    for (int kt = 0; kt < 64; kt++) {
        cp_wait<1>();
        __syncthreads();   // single barrier: both warps done with tile kt-1 (slot2's occupant)

        // refill slot of tile kt-1 with tile kt+2 (safe: consumed before this barrier)
        if (kt + 2 < 64)
            attn_stage_issue(sb + slot2 * AT_STAGE, ph, gg,
                             ((kt + 2 + phase) & 63) * 64, tid);
        cp_commit();   // uniform group count

        const uint32_t SB = sb + slot * AT_STAGE;

        #pragma unroll
        for (int h = 0; h < 2; h++) {
            float s[2][4][4];
            #pragma unroll
            for (int ar = 0; ar < 2; ar++)
                #pragma unroll
                for (int i = 0; i < 4; i++)
                    #pragma unroll
                    for (int j = 0; j < 4; j++) s[ar][i][j] = 0.f;

            #pragma unroll
            for (int kc = 0; kc < 4; kc++) {
                #pragma unroll
                for (int kyg = 0; kyg < 2; kyg++) {
                    uint32_t bh[4];
                    ldmx4t(bh, SB + ((kc * 16 + bkr) * 72 + h * 32 + kyg * 16 + bnc) * 2);
                    #pragma unroll
                    for (int ar = 0; ar < 2; ar++) {
                        mma_f16(s[ar][2 * kyg],     a[kc][ar], bh);
                        mma_f16(s[ar][2 * kyg + 1], a[kc][ar], bh + 2);
                    }
                }
            }

            uint32_t pe[2][4][2];
            #pragma unroll
            for (int ar = 0; ar < 2; ar++) {
                #pragma unroll
                for (int j = 0; j < 4; j++) {
                    pe[ar][j][0] = exp2_off16(pack_f16x2(s[ar][j][0], s[ar][j][1]));
                    pe[ar][j][1] = exp2_off16(pack_f16x2(s[ar][j][2], s[ar][j][3]));
                }
                uint32_t t0 = hadd2u(hadd2u(pe[ar][0][0], pe[ar][1][0]),
                                     hadd2u(pe[ar][2][0], pe[ar][3][0]));
                uint32_t t1 = hadd2u(hadd2u(pe[ar][0][1], pe[ar][1][1]),
                                     hadd2u(pe[ar][2][1], pe[ar][3][1]));
                float2 f0 = h2_to_f2(t0), f1 = h2_to_f2(t1);
                rs[ar][0] += f0.x + f0.y;
                rs[ar][1] += f1.x + f1.y;
            }

            #pragma unroll
            for (int kkc = 0; kkc < 2; kkc++) {
                #pragma unroll
                for (int cg = 0; cg < 4; cg++) {
                    uint32_t bg[4];
                    ldmx4(bg, SB + AT_TILE +
                              ((cg * 16 + lmr) * 72 + h * 32 + kkc * 16 + lmc) * 2);
                    #pragma unroll
                    for (int ar = 0; ar < 2; ar++) {
                        uint32_t pa[4] = { pe[ar][2 * kkc][0],     pe[ar][2 * kkc][1],
                                           pe[ar][2 * kkc + 1][0], pe[ar][2 * kkc + 1][1] };
                        mma_f16(yacc[ar][2 * cg],     pa, bg);
                        mma_f16(yacc[ar][2 * cg + 1], pa, bg + 2);
                    }
                }
            }
        }

        slot  = (slot  == 2) ? 0 : slot  + 1;
        slot2 = (slot2 == 2) ? 0 : slot2 + 1;
    }

    #pragma unroll
    for (int ar = 0; ar < 2; ar++)
        #pragma unroll
        for (int r = 0; r < 2; r++) {
            float v = rs[ar][r];
            v += __shfl_xor_sync(0xFFFFFFFFu, v, 1);
            v += __shfl_xor_sync(0xFFFFFFFFu, v, 2);
            rs[ar][r] = 1.f / v;
        }

    #pragma unroll
    for (int ar = 0; ar < 2; ar++) {
        const int q0 = nt * 64 + wid * 32 + ar * 16;
        __half* yp = d_y + ((size_t)b * N_ + q0) * CI_;
        const float i0 = rs[ar][0], i1 = rs[ar][1];
        #pragma unroll
        for (int nf = 0; nf < 8; nf++) {
            int c = nf * 8 + lc * 2;
            *(uint32_t*)(yp + (size_t)lr * CI_ + c) =
                pack_f16x2(yacc[ar][nf][0] * i0, yacc[ar][nf][1] * i0);
            *(uint32_t*)(yp + (size_t)(lr + 8) * CI_ + c) =
                pack_f16x2(yacc[ar][nf][2] * i1, yacc[ar][nf][3] * i1);
        }
    }
}

// ============== Kernel 3: output conv + residual (direct epilogue) ==============
constexpr int WC_W    = 0;       // [128 co][64 ci] fp16, stride 72 elems (144B)
constexpr int WC_Y    = 18432;   // [128 n][64 ci] fp16
constexpr int WC_SMEM = 36864;

__global__ __launch_bounds__(256) void wconv_kernel(
    const float* __restrict__ x,  const float* __restrict__ w2,
    const float* __restrict__ wb, float* __restrict__ out)
{
    extern __shared__ char sm[];
    const uint32_t sb = smem_u32(sm);
    const int tid = threadIdx.x;
    const int wid = tid >> 5, lane = tid & 31;
    const int nt = blockIdx.x, ct = blockIdx.y, b = blockIdx.z;
    const int lr = lane >> 2, lc = lane & 3;

    #pragma unroll
    for (int j = 0; j < 8; j++) {
        int idx = tid + j * 256;          // 0..2047
        int row = idx >> 4, c4 = idx & 15;
        float4 v = *(const float4*)(w2 + (size_t)(ct * 128 + row) * CI_ + c4 * 4);
        uint2 o = { pack_f16x2(v.x, v.y), pack_f16x2(v.z, v.w) };
        *(uint2*)(sm + WC_W + row * 144 + c4 * 8) = o;
    }
    #pragma unroll
    for (int j = 0; j < 4; j++) {
        int idx = tid + j * 256;          // 0..1023
        int row = idx >> 3, c16 = idx & 7;
        *(uint4*)(sm + WC_Y + row * 144 + c16 * 16) =
            *(const uint4*)(d_y + ((size_t)b * N_ + nt * 128 + row) * CI_ + c16 * 8);
    }
    __syncthreads();

    const int mi = wid & 3, nh = wid >> 2;
    const int amr = (lane & 7) + ((lane >> 3) & 1) * 8;
    const int akc = (lane >> 4) * 8;
    const int lmr = ((lane >> 4) << 3) + (lane & 7);
    const int lmc = ((lane >> 3) & 1) * 8;

    float acc[2][8][4];
    #pragma unroll
    for (int m = 0; m < 2; m++)
        #pragma unroll
        for (int i = 0; i < 8; i++)
            #pragma unroll
            for (int j = 0; j < 4; j++) acc[m][i][j] = 0.f;

    #pragma unroll
    for (int ks = 0; ks < 4; ks++) {
        uint32_t ah[2][4];
        #pragma unroll
        for (int m = 0; m < 2; m++)
            ldmx4(ah[m], sb + WC_W + ((mi * 32 + m * 16 + amr) * 72 + ks * 16 + akc) * 2);
        #pragma unroll
        for (int nf4 = 0; nf4 < 4; nf4++) {
            uint32_t bh[4];
            ldmx4(bh, sb + WC_Y + ((nh * 64 + nf4 * 16 + lmr) * 72 + ks * 16 + lmc) * 2);
            #pragma unroll
            for (int m = 0; m < 2; m++) {
                mma_f16(acc[m][2 * nf4],     ah[m], bh);
                mma_f16(acc[m][2 * nf4 + 1], ah[m], bh + 2);
            }
        }
    }

    #pragma unroll
    for (int m = 0; m < 2; m++) {
        int co0 = ct * 128 + mi * 32 + m * 16 + lr;
        float bv0 = wb[co0], bv1 = wb[co0 + 8];
        #pragma unroll
        for (int nf = 0; nf < 8; nf++) {
            size_t n = (size_t)nt * 128 + nh * 64 + nf * 8 + lc * 2;
            size_t base0 = ((size_t)b * C_ + co0) * N_ + n;
            size_t base1 = ((size_t)b * C_ + co0 + 8) * N_ + n;
            float2 x0 = *(const float2*)(x + base0);
            float2 x1 = *(const float2*)(x + base1);
            *(float2*)(out + base0) =
                make_float2(acc[m][nf][0] + bv0 + x0.x, acc[m][nf][1] + bv0 + x0.y);
            *(float2*)(out + base1) =
                make_float2(acc[m][nf][2] + bv1 + x1.x, acc[m][nf][3] + bv1 + x1.y);
        }
    }
}

// ---------------------------------------------------------------------------
extern "C" void kernel_launch(void* const* d_in, const int* in_sizes, int n_in,
                              void* d_out, int out_size)
{
    const float* x  = (const float*)d_in[0];
    const float* gw = (const float*)d_in[1];
    const float* gb = (const float*)d_in[2];
    const float* tw = (const float*)d_in[3];
    const float* tb = (const float*)d_in[4];
    const float* pw = (const float*)d_in[5];
    const float* pb = (const float*)d_in[6];
    const float* ww = (const float*)d_in[7];
    const float* wb = (const float*)d_in[8];
    float* out = (float*)d_out;

    cudaFuncSetAttribute(proj_kernel,  cudaFuncAttributeMaxDynamicSharedMemorySize, PJ_SMEM);
    cudaFuncSetAttribute(attn_kernel,  cudaFuncAttributeMaxDynamicSharedMemorySize, AT_SMEM);
    cudaFuncSetAttribute(wconv_kernel, cudaFuncAttributeMaxDynamicSharedMemorySize, WC_SMEM);

    proj_kernel<<<dim3(N_ / 64, B_), 384, PJ_SMEM>>>(x, tw, pw, gw, tb, pb, gb);
    attn_kernel<<<dim3(N_ / 64, B_), 64, AT_SMEM>>>();
    wconv_kernel<<<dim3(N_ / 128, 2, B_), 256, WC_SMEM>>>(x, ww, wb, out);
}

// round 15
// speedup vs baseline: 1.0300x; 1.0300x over previous
#include <cuda_runtime.h>
#include <cuda_fp16.h>
#include <cstdint>

// Problem constants
constexpr int B_  = 8;
constexpr int C_  = 256;
constexpr int CI_ = 64;
constexpr int N_  = 4096;   // H*W
constexpr float LOG2E = 1.4426950408889634f;
constexpr uint32_t H2_OFF16 = 0x4C004C00u;   // f16x2 {16.0, 16.0}

// ---------------- scratch (device globals: allocation-free rule) ----------------
__device__ __half d_th[B_ * CI_ * N_];  // theta fp16 (pre-scaled by log2e) [b][ci][n]
__device__ __half d_ph[B_ * CI_ * N_];  // phi fp16 [b][ci][n]
__device__ __half d_g [B_ * CI_ * N_];  // g fp16 [b][ci][n]

// ---------------- helpers ----------------
__device__ __forceinline__ uint32_t smem_u32(const void* p) {
    uint32_t a;
    asm("{ .reg .u64 t; cvta.to.shared.u64 t, %1; cvt.u32.u64 %0, t; }" : "=r"(a) : "l"(p));
    return a;
}
__device__ __forceinline__ void mma_f16(float* c, const uint32_t* a, const uint32_t* b) {
    asm volatile(
        "mma.sync.aligned.m16n8k16.row.col.f32.f16.f16.f32 "
        "{%0,%1,%2,%3}, {%4,%5,%6,%7}, {%8,%9}, {%0,%1,%2,%3};"
        : "+f"(c[0]), "+f"(c[1]), "+f"(c[2]), "+f"(c[3])
        : "r"(a[0]), "r"(a[1]), "r"(a[2]), "r"(a[3]), "r"(b[0]), "r"(b[1]));
}
__device__ __forceinline__ void ldmx4(uint32_t* r, uint32_t addr) {
    asm volatile("ldmatrix.sync.aligned.m8n8.x4.shared.b16 {%0,%1,%2,%3}, [%4];"
                 : "=r"(r[0]), "=r"(r[1]), "=r"(r[2]), "=r"(r[3]) : "r"(addr));
}
__device__ __forceinline__ void ldmx4t(uint32_t* r, uint32_t addr) {
    asm volatile("ldmatrix.sync.aligned.m8n8.x4.trans.shared.b16 {%0,%1,%2,%3}, [%4];"
                 : "=r"(r[0]), "=r"(r[1]), "=r"(r[2]), "=r"(r[3]) : "r"(addr));
}
__device__ __forceinline__ uint32_t pack_f16x2(float lo, float hi) {
    uint32_t r;
    asm("cvt.rn.f16x2.f32 %0, %1, %2;" : "=r"(r) : "f"(hi), "f"(lo));
    return r;
}
__device__ __forceinline__ uint32_t exp2_off16(uint32_t h2) {
    asm("sub.f16x2 %0, %0, %1;" : "+r"(h2) : "r"(H2_OFF16));
    asm("ex2.approx.f16x2 %0, %0;" : "+r"(h2));
    return h2;
}
__device__ __forceinline__ uint32_t hadd2u(uint32_t a, uint32_t b) {
    uint32_t r;
    asm("add.f16x2 %0, %1, %2;" : "=r"(r) : "r"(a), "r"(b));
    return r;
}
__device__ __forceinline__ float2 h2_to_f2(uint32_t h2) {
    __half2 h = *reinterpret_cast<__half2*>(&h2);
    return __half22float2(h);
}
__device__ __forceinline__ void cp16(uint32_t s, const void* g) {
    asm volatile("cp.async.cg.shared.global [%0], [%1], 16;" :: "r"(s), "l"(g));
}
__device__ __forceinline__ void cp_commit() { asm volatile("cp.async.commit_group;"); }
template <int n> __device__ __forceinline__ void cp_wait() {
    asm volatile("cp.async.wait_group %0;" :: "n"(n));
}

// ============== Kernel 1: FUSED projections (one x pass, 3 weight sets) ==============
constexpr int PJ_WS   = 0;          // 3 * 64 * 272 = 52224
constexpr int PJ_XS   = 52224;      // 128 * 144   = 18432
constexpr int PJ_SMEM = 70656;

__global__ __launch_bounds__(384, 2) void proj_kernel(
    const float* __restrict__ x,
    const float* __restrict__ tw, const float* __restrict__ pw,
    const float* __restrict__ gw,
    const float* __restrict__ tb, const float* __restrict__ pb,
    const float* __restrict__ gb)
{
    extern __shared__ char sm[];
    const uint32_t sb = smem_u32(sm);
    const int tid = threadIdx.x;
    const int wid = tid >> 5, lane = tid & 31;
    const int nt = blockIdx.x, b = blockIdx.y;
    const int lr = lane >> 2, lc = lane & 3;

    const float* wsrc[3] = { tw, pw, gw };
    const float* xsrc = x + (size_t)b * C_ * N_ + nt * 64;

    const int pj = wid >> 2, mi = wid & 3;
    const int amr = (lane & 7) + ((lane >> 3) & 1) * 8;
    const int akc = (lane >> 4) * 8;
    const int bkr = ((lane >> 3) & 1) * 8 + (lane & 7);
    const int bnc = (lane >> 4) * 8;

    float acc[8][4];
    #pragma unroll
    for (int i = 0; i < 8; i++)
        #pragma unroll
        for (int j = 0; j < 4; j++) acc[i][j] = 0.f;

    const uint32_t ws_base = sb + PJ_WS + pj * 17408;

    for (int ch = 0; ch < 2; ch++) {
        __syncthreads();
        #pragma unroll
        for (int j = 0; j < 16; j++) {
            int idx = tid + j * 384;          // 0..6143
            int row = idx >> 5, c4 = idx & 31;
            int p = row >> 6, r = row & 63;
            float4 v = *(const float4*)(wsrc[p] + (size_t)r * C_ + ch * 128 + c4 * 4);
            uint2 o = { pack_f16x2(v.x, v.y), pack_f16x2(v.z, v.w) };
            *(uint2*)(sm + PJ_WS + p * 17408 + r * 272 + c4 * 8) = o;
        }
        #pragma unroll
        for (int j = 0; j < 6; j++) {
            int idx = tid + j * 384;          // guard at 2048
            if (idx < 2048) {
                int row = idx >> 4, c4 = idx & 15;
                float4 v = *(const float4*)(xsrc + (size_t)(ch * 128 + row) * N_ + c4 * 4);
                uint2 o = { pack_f16x2(v.x, v.y), pack_f16x2(v.z, v.w) };
                *(uint2*)(sm + PJ_XS + row * 144 + c4 * 8) = o;
            }
        }
        __syncthreads();

        #pragma unroll
        for (int ks = 0; ks < 8; ks++) {
            uint32_t a[4];
            ldmx4(a, ws_base + ((mi * 16 + amr) * 136 + ks * 16 + akc) * 2);
            #pragma unroll
            for (int nf4 = 0; nf4 < 4; nf4++) {
                uint32_t bb[4];
                ldmx4t(bb, sb + PJ_XS +
                           ((ks * 16 + bkr) * 72 + nf4 * 16 + bnc) * 2);
                mma_f16(acc[2 * nf4],     a, bb);
                mma_f16(acc[2 * nf4 + 1], a, bb + 2);
            }
        }
    }

    const float* bias = (pj == 0) ? tb : (pj == 1) ? pb : gb;
    const int ci0 = mi * 16 + lr;
    const float bv0 = bias[ci0], bv1 = bias[ci0 + 8];
    const float sc = (pj == 0) ? LOG2E : 1.f;

    __half* out = (pj == 0 ? d_th : (pj == 1 ? d_ph : d_g)) + (size_t)b * CI_ * N_;
    #pragma unroll
    for (int nf = 0; nf < 8; nf++) {
        size_t n = (size_t)nt * 64 + nf * 8 + lc * 2;
        *(uint32_t*)(out + (size_t)ci0 * N_ + n) =
            pack_f16x2((acc[nf][0] + bv0) * sc, (acc[nf][1] + bv0) * sc);
        *(uint32_t*)(out + (size_t)(ci0 + 8) * N_ + n) =
            pack_f16x2((acc[nf][2] + bv1) * sc, (acc[nf][3] + bv1) * sc);
    }
}

// ============== Kernel 2: flash attention + fused output conv + residual ==============
constexpr int AT_TILE  = 9216;       // 64*144
constexpr int AT_STAGE = 18432;      // 2 tiles (phi + g)
constexpr int AT_SMEM  = 55296;      // 3 stages; epilogue reuses for w2 [256][72] = 36864B

__device__ __forceinline__ void attn_stage_issue(
    uint32_t sbase, const __half* ph, const __half* gg, int koff, int tid)
{
    #pragma unroll
    for (int j = 0; j < 8; j++) {
        int idx = tid + j * 64;              // 0..511
        int row = idx >> 3, c16 = idx & 7;
        uint32_t so = row * 144 + c16 * 16;
        cp16(sbase + so,           ph + (size_t)row * N_ + koff + c16 * 8);
        cp16(sbase + AT_TILE + so, gg + (size_t)row * N_ + koff + c16 * 8);
    }
}

__global__ __launch_bounds__(64, 4) void attn_kernel(
    const float* __restrict__ x,  const float* __restrict__ w2,
    const float* __restrict__ wb, float* __restrict__ out)
{
    extern __shared__ char sm[];
    const uint32_t sb = smem_u32(sm);
    const int tid = threadIdx.x;
    const int wid = tid >> 5, lane = tid & 31;
    const int nt = blockIdx.x;   // 64-query tile (0..63)
    const int b  = blockIdx.y;
    const int lr = lane >> 2, lc = lane & 3;
    const int phase = (nt & 3) << 4;   // rotated key-tile start

    const __half* ph = d_ph + (size_t)b * CI_ * N_;
    const __half* gg = d_g  + (size_t)b * CI_ * N_;
    const __half* th = d_th + (size_t)b * CI_ * N_ + nt * 64;

    // ---- theta A-frags via stage-0 region ----
    const int tkr = (lane >> 4) * 8 + (lane & 7);
    const int tmc = ((lane >> 3) & 1) * 8;
    uint32_t a[4][2][4];   // [kc][arow][frag]
    {
        #pragma unroll
        for (int j = 0; j < 8; j++) {
            int idx = tid + j * 64;
            int row = idx >> 3, c16 = idx & 7;
            *(uint4*)(sm + row * 144 + c16 * 16) =
                *(const uint4*)(th + (size_t)row * N_ + c16 * 8);
        }
        __syncthreads();
        #pragma unroll
        for (int kc = 0; kc < 4; kc++)
            #pragma unroll
            for (int ar = 0; ar < 2; ar++)
                ldmx4t(a[kc][ar],
                       sb + ((kc * 16 + tkr) * 72 + wid * 32 + ar * 16 + tmc) * 2);
        __syncthreads();
    }

    // prefetch tiles 0,1 into slots 0,1
    attn_stage_issue(sb,            ph, gg, ((0 + phase) & 63) * 64, tid); cp_commit();
    attn_stage_issue(sb + AT_STAGE, ph, gg, ((1 + phase) & 63) * 64, tid); cp_commit();

    const int bkr = ((lane >> 3) & 1) * 8 + (lane & 7);   // trans (phi)
    const int bnc = (lane >> 4) * 8;
    const int lmr = ((lane >> 4) << 3) + (lane & 7);      // non-trans (g)
    const int lmc = ((lane >> 3) & 1) * 8;

    float yacc[2][8][4];
    #pragma unroll
    for (int ar = 0; ar < 2; ar++)
        #pragma unroll
        for (int i = 0; i < 8; i++)
            #pragma unroll
            for (int j = 0; j < 4; j++) yacc[ar][i][j] = 0.f;
    float rs[2][2] = {{0.f, 0.f}, {0.f, 0.f}};

    int slot = 0, slot2 = 2;
    for (int kt = 0; kt < 64; kt++) {
        cp_wait<1>();
        __syncthreads();

        if (kt + 2 < 64)
            attn_stage_issue(sb + slot2 * AT_STAGE, ph, gg,
                             ((kt + 2 + phase) & 63) * 64, tid);
        cp_commit();

        const uint32_t SB = sb + slot * AT_STAGE;

        #pragma unroll
        for (int h = 0; h < 2; h++) {
            float s[2][4][4];
            #pragma unroll
            for (int ar = 0; ar < 2; ar++)
                #pragma unroll
                for (int i = 0; i < 4; i++)
                    #pragma unroll
                    for (int j = 0; j < 4; j++) s[ar][i][j] = 0.f;

            #pragma unroll
            for (int kc = 0; kc < 4; kc++) {
                #pragma unroll
                for (int kyg = 0; kyg < 2; kyg++) {
                    uint32_t bh[4];
                    ldmx4t(bh, SB + ((kc * 16 + bkr) * 72 + h * 32 + kyg * 16 + bnc) * 2);
                    #pragma unroll
                    for (int ar = 0; ar < 2; ar++) {
                        mma_f16(s[ar][2 * kyg],     a[kc][ar], bh);
                        mma_f16(s[ar][2 * kyg + 1], a[kc][ar], bh + 2);
                    }
                }
            }

            uint32_t pe[2][4][2];
            #pragma unroll
            for (int ar = 0; ar < 2; ar++) {
                #pragma unroll
                for (int j = 0; j < 4; j++) {
                    pe[ar][j][0] = exp2_off16(pack_f16x2(s[ar][j][0], s[ar][j][1]));
                    pe[ar][j][1] = exp2_off16(pack_f16x2(s[ar][j][2], s[ar][j][3]));
                }
                uint32_t t0 = hadd2u(hadd2u(pe[ar][0][0], pe[ar][1][0]),
                                     hadd2u(pe[ar][2][0], pe[ar][3][0]));
                uint32_t t1 = hadd2u(hadd2u(pe[ar][0][1], pe[ar][1][1]),
                                     hadd2u(pe[ar][2][1], pe[ar][3][1]));
                float2 f0 = h2_to_f2(t0), f1 = h2_to_f2(t1);
                rs[ar][0] += f0.x + f0.y;
                rs[ar][1] += f1.x + f1.y;
            }

            #pragma unroll
            for (int kkc = 0; kkc < 2; kkc++) {
                #pragma unroll
                for (int cg = 0; cg < 4; cg++) {
                    uint32_t bg[4];
                    ldmx4(bg, SB + AT_TILE +
                              ((cg * 16 + lmr) * 72 + h * 32 + kkc * 16 + lmc) * 2);
                    #pragma unroll
                    for (int ar = 0; ar < 2; ar++) {
                        uint32_t pa[4] = { pe[ar][2 * kkc][0],     pe[ar][2 * kkc][1],
                                           pe[ar][2 * kkc + 1][0], pe[ar][2 * kkc + 1][1] };
                        mma_f16(yacc[ar][2 * cg],     pa, bg);
                        mma_f16(yacc[ar][2 * cg + 1], pa, bg + 2);
                    }
                }
            }
        }

        slot  = (slot  == 2) ? 0 : slot  + 1;
        slot2 = (slot2 == 2) ? 0 : slot2 + 1;
    }

    // ---- rowsum reduce + invert ----
    #pragma unroll
    for (int ar = 0; ar < 2; ar++)
        #pragma unroll
        for (int r = 0; r < 2; r++) {
            float v = rs[ar][r];
            v += __shfl_xor_sync(0xFFFFFFFFu, v, 1);
            v += __shfl_xor_sync(0xFFFFFFFFu, v, 2);
            rs[ar][r] = 1.f / v;
        }

    // ---- normalize + convert y C-frags into B-frags of y^T (C==B^T layout identity) ----
    // yb[ar][h][kc][2]: B-frag {b0,b1} for k-chunk kc (ci 16kc..+15), n-block (ar,h)
    uint32_t yb[2][2][4][2];
    #pragma unroll
    for (int ar = 0; ar < 2; ar++) {
        const float i0 = rs[ar][0], i1 = rs[ar][1];
        #pragma unroll
        for (int kc = 0; kc < 4; kc++) {
            yb[ar][0][kc][0] = pack_f16x2(yacc[ar][2 * kc][0] * i0,     yacc[ar][2 * kc][1] * i0);
            yb[ar][0][kc][1] = pack_f16x2(yacc[ar][2 * kc + 1][0] * i0, yacc[ar][2 * kc + 1][1] * i0);
            yb[ar][1][kc][0] = pack_f16x2(yacc[ar][2 * kc][2] * i1,     yacc[ar][2 * kc][3] * i1);
            yb[ar][1][kc][1] = pack_f16x2(yacc[ar][2 * kc + 1][2] * i1, yacc[ar][2 * kc + 1][3] * i1);
        }
    }

    // ---- stage w2 [256 co][64 ci] fp32 -> fp16 into (drained) pipeline smem ----
    cp_wait<0>();
    __syncthreads();
    #pragma unroll
    for (int j = 0; j < 64; j++) {
        int idx = tid + j * 64;           // 0..4095 float4
        int row = idx >> 4, c4 = idx & 15;
        float4 v = *(const float4*)(w2 + (size_t)row * CI_ + c4 * 4);
        uint2 o = { pack_f16x2(v.x, v.y), pack_f16x2(v.z, v.w) };
        *(uint2*)(sm + row * 144 + c4 * 8) = o;
    }
    __syncthreads();

    // ---- out[co][q] = w2 . y^T + wb + x, in co chunks of 64 ----
    const int amr = (lane & 7) + ((lane >> 3) & 1) * 8;
    const int akc = (lane >> 4) * 8;
    #pragma unroll
    for (int ct = 0; ct < 4; ct++) {
        float oa[4][4][4];   // [mt][nb][frag]
        #pragma unroll
        for (int mt = 0; mt < 4; mt++)
            #pragma unroll
            for (int nb = 0; nb < 4; nb++)
                #pragma unroll
                for (int j = 0; j < 4; j++) oa[mt][nb][j] = 0.f;

        #pragma unroll
        for (int mt = 0; mt < 4; mt++) {
            uint32_t aw[4][4];
            #pragma unroll
            for (int kc = 0; kc < 4; kc++)
                ldmx4(aw[kc], sb + ((ct * 64 + mt * 16 + amr) * 72 + kc * 16 + akc) * 2);
            #pragma unroll
            for (int nb = 0; nb < 4; nb++) {
                int ar = nb >> 1, h = nb & 1;
                #pragma unroll
                for (int kc = 0; kc < 4; kc++)
                    mma_f16(oa[mt][nb], aw[kc], yb[ar][h][kc]);
            }
        }

        // store with bias + residual
        #pragma unroll
        for (int mt = 0; mt < 4; mt++) {
            int co0 = ct * 64 + mt * 16 + lr;
            float bv0 = wb[co0], bv1 = wb[co0 + 8];
            #pragma unroll
            for (int nb = 0; nb < 4; nb++) {
                int ar = nb >> 1, h = nb & 1;
                size_t q = (size_t)nt * 64 + wid * 32 + ar * 16 + h * 8 + lc * 2;
                size_t base0 = ((size_t)b * C_ + co0) * N_ + q;
                size_t base1 = base0 + (size_t)8 * N_;
                float2 x0 = *(const float2*)(x + base0);
                float2 x1 = *(const float2*)(x + base1);
                *(float2*)(out + base0) =
                    make_float2(oa[mt][nb][0] + bv0 + x0.x, oa[mt][nb][1] + bv0 + x0.y);
                *(float2*)(out + base1) =
                    make_float2(oa[mt][nb][2] + bv1 + x1.x, oa[mt][nb][3] + bv1 + x1.y);
            }
        }
    }
}

// ---------------------------------------------------------------------------
extern "C" void kernel_launch(void* const* d_in, const int* in_sizes, int n_in,
                              void* d_out, int out_size)
{
    const float* x  = (const float*)d_in[0];
    const float* gw = (const float*)d_in[1];
    const float* gb = (const float*)d_in[2];
    const float* tw = (const float*)d_in[3];
    const float* tb = (const float*)d_in[4];
    const float* pw = (const float*)d_in[5];
    const float* pb = (const float*)d_in[6];
    const float* ww = (const float*)d_in[7];
    const float* wb = (const float*)d_in[8];
    float* out = (float*)d_out;

    cudaFuncSetAttribute(proj_kernel, cudaFuncAttributeMaxDynamicSharedMemorySize, PJ_SMEM);
    cudaFuncSetAttribute(attn_kernel, cudaFuncAttributeMaxDynamicSharedMemorySize, AT_SMEM);

    proj_kernel<<<dim3(N_ / 64, B_), 384, PJ_SMEM>>>(x, tw, pw, gw, tb, pb, gb);
    attn_kernel<<<dim3(N_ / 64, B_), 64, AT_SMEM>>>(x, ww, wb, out);
}